// round 8
// baseline (speedup 1.0000x reference)
#include <cuda_runtime.h>

// TransD forward, simplified (eye is identity, RD==ED):
//   h_out = renorm(rp) * <renorm(hp), renorm(hv)> + renorm(hv)
//   rv_out = renorm(rv)
//   t_out = renorm(rp) * <renorm(tp), renorm(tv)> + renorm(tv)
//
// One warp per sample, lane owns one float4.
// Value-packing reduction tree: 8 simultaneous warp sums in 9 SHFLs
// (fold values into lanes at each butterfly level), +8 broadcasts.

#define NB 8192
#define DV 32u  // float4s per 128-float row
#define FULL 0xffffffffu

__device__ __forceinline__ float dot4(float4 a, float4 b) {
    return a.x * b.x + a.y * b.y + a.z * b.z + a.w * b.w;
}

__device__ __forceinline__ float rscale(float sumsq) {
    float n = sqrtf(sumsq);
    return (n > 1.0f) ? (1.0f / (n + 1e-7f)) : 1.0f;
}

__device__ __forceinline__ void st_cs(float4* p, float4 v) {
    asm volatile("st.global.cs.v4.f32 [%0], {%1,%2,%3,%4};"
                 :: "l"(p), "f"(v.x), "f"(v.y), "f"(v.z), "f"(v.w) : "memory");
}

__global__ __launch_bounds__(256) void transd_kernel(
    const float4* __restrict__ ee,   // entity_emb      [ENT*32]
    const float4* __restrict__ eep,  // entity_emb_p    [ENT*32]
    const float4* __restrict__ re,   // relation_emb    [REL*32]
    const float4* __restrict__ rep,  // relation_emb_p  [REL*32]
    const int* __restrict__ h,
    const int* __restrict__ r,
    const int* __restrict__ t,
    float4* __restrict__ out)        // [3 * NB * 32]
{
    int gwarp = (blockIdx.x * blockDim.x + threadIdx.x) >> 5;
    unsigned lane = threadIdx.x & 31u;
    if (gwarp >= NB) return;

    int hi = __ldg(&h[gwarp]);
    int ri = __ldg(&r[gwarp]);
    int ti = __ldg(&t[gwarp]);

    unsigned oh  = (unsigned)hi * DV + lane;
    unsigned ot  = (unsigned)ti * DV + lane;
    unsigned orr = (unsigned)ri * DV + lane;

    // all 6 gathers issued up front (max MLP)
    float4 hv = __ldg(ee  + oh);
    float4 hp = __ldg(eep + oh);
    float4 tv = __ldg(ee  + ot);
    float4 tp = __ldg(eep + ot);
    float4 rv = __ldg(re  + orr);
    float4 rp = __ldg(rep + orr);

    // 8 per-lane partials:
    // 0:|hv|² 1:|hp|² 2:|tv|² 3:|tp|² 4:|rv|² 5:|rp|² 6:<hp,hv> 7:<tp,tv>
    float p0 = dot4(hv, hv);
    float p1 = dot4(hp, hp);
    float p2 = dot4(tv, tv);
    float p3 = dot4(tp, tp);
    float p4 = dot4(rv, rv);
    float p5 = dot4(rp, rp);
    float p6 = dot4(hp, hv);
    float p7 = dot4(tp, tv);

    bool b0 = lane & 1u;
    bool b1 = lane & 2u;
    bool b2 = lane & 4u;

    // Level 1 (xor 1): 8 -> 4 values. q_i = value (2i + bit0), summed over pair.
    float q0 = (b0 ? p1 : p0) + __shfl_xor_sync(FULL, b0 ? p0 : p1, 1);
    float q1 = (b0 ? p3 : p2) + __shfl_xor_sync(FULL, b0 ? p2 : p3, 1);
    float q2 = (b0 ? p5 : p4) + __shfl_xor_sync(FULL, b0 ? p4 : p5, 1);
    float q3 = (b0 ? p7 : p6) + __shfl_xor_sync(FULL, b0 ? p6 : p7, 1);

    // Level 2 (xor 2): 4 -> 2. u_i = value (4i + 2*bit1 + bit0), over 4 lanes.
    float u0 = (b1 ? q1 : q0) + __shfl_xor_sync(FULL, b1 ? q0 : q1, 2);
    float u1 = (b1 ? q3 : q2) + __shfl_xor_sync(FULL, b1 ? q2 : q3, 2);

    // Level 3 (xor 4): 2 -> 1. w = value (lane&7), summed over 8 lanes.
    float w = (b2 ? u1 : u0) + __shfl_xor_sync(FULL, b2 ? u0 : u1, 4);

    // Levels 4,5: finish the 32-lane sum.
    w += __shfl_xor_sync(FULL, w, 8);
    w += __shfl_xor_sync(FULL, w, 16);
    // every lane holds total_{lane&7}

    // one rscale chain per lane (values 6,7 get a harmless rscale too)
    float rs = rscale(w);

    float c_hv = __shfl_sync(FULL, rs, 0);
    float c_hp = __shfl_sync(FULL, rs, 1);
    float c_tv = __shfl_sync(FULL, rs, 2);
    float c_tp = __shfl_sync(FULL, rs, 3);
    float c_rv = __shfl_sync(FULL, rs, 4);
    float c_rp = __shfl_sync(FULL, rs, 5);
    float d_h  = __shfl_sync(FULL, w, 6);
    float d_t  = __shfl_sync(FULL, w, 7);

    float a_h = c_rp * (d_h * c_hp * c_hv);
    float a_t = c_rp * (d_t * c_tp * c_tv);

    unsigned base = (unsigned)gwarp * DV + lane;

    float4 o;
    o.x = rp.x * a_h + hv.x * c_hv;
    o.y = rp.y * a_h + hv.y * c_hv;
    o.z = rp.z * a_h + hv.z * c_hv;
    o.w = rp.w * a_h + hv.w * c_hv;
    st_cs(&out[base], o);

    o.x = rv.x * c_rv; o.y = rv.y * c_rv; o.z = rv.z * c_rv; o.w = rv.w * c_rv;
    st_cs(&out[NB * DV + base], o);

    o.x = rp.x * a_t + tv.x * c_tv;
    o.y = rp.y * a_t + tv.y * c_tv;
    o.z = rp.z * a_t + tv.z * c_tv;
    o.w = rp.w * a_t + tv.w * c_tv;
    st_cs(&out[2u * NB * DV + base], o);
}

extern "C" void kernel_launch(void* const* d_in, const int* in_sizes, int n_in,
                              void* d_out, int out_size) {
    const float4* ee  = (const float4*)d_in[0];
    const float4* eep = (const float4*)d_in[1];
    const float4* re  = (const float4*)d_in[2];
    const float4* rep = (const float4*)d_in[3];
    const int* h = (const int*)d_in[4];
    const int* r = (const int*)d_in[5];
    const int* t = (const int*)d_in[6];

    // 8 warps (256 threads) per block, 1 sample per warp -> 1024 blocks
    int blocks = (NB * 32 + 255) / 256;
    transd_kernel<<<blocks, 256>>>(ee, eep, re, rep, h, r, t, (float4*)d_out);
}

// round 9
// speedup vs baseline: 1.0295x; 1.0295x over previous
#include <cuda_runtime.h>
#include <cstdint>

// TransD forward, simplified (eye is identity, RD==ED):
//   h_out = renorm(rp) * <renorm(hp), renorm(hv)> + renorm(hv)
//   rv_out = renorm(rv)
//   t_out = renorm(rp) * <renorm(tp), renorm(tv)> + renorm(tv)
//
// One warp per sample. Gathers go through cp.async.bulk (TMA bulk engine,
// deep outstanding-request queue) into SMEM instead of LDG (LSU queue-bound).
// mbarrier completion per warp, then 9-SHFL packed reduction.

#define NB 8192
#define DV 32u          // float4s per 128-float row
#define ROW_BYTES 512u  // 128 floats
#define FULL 0xffffffffu
#define WPB 4           // warps per block (128 threads)

__device__ __forceinline__ float dot4(float4 a, float4 b) {
    return a.x * b.x + a.y * b.y + a.z * b.z + a.w * b.w;
}

__device__ __forceinline__ float rscale(float sumsq) {
    float n = sqrtf(sumsq);
    return (n > 1.0f) ? (1.0f / (n + 1e-7f)) : 1.0f;
}

__device__ __forceinline__ void st_cs(float4* p, float4 v) {
    asm volatile("st.global.cs.v4.f32 [%0], {%1,%2,%3,%4};"
                 :: "l"(p), "f"(v.x), "f"(v.y), "f"(v.z), "f"(v.w) : "memory");
}

__device__ __forceinline__ uint32_t smem_u32(const void* p) {
    uint32_t a;
    asm("{ .reg .u64 tmp; cvta.to.shared.u64 tmp, %1; cvt.u32.u64 %0, tmp; }"
        : "=r"(a) : "l"(p));
    return a;
}

__device__ __forceinline__ void bulk_cp(uint32_t dst_smem, const void* src,
                                        uint32_t bytes, uint32_t mbar) {
    asm volatile(
        "cp.async.bulk.shared::cluster.global.mbarrier::complete_tx::bytes "
        "[%0], [%1], %2, [%3];"
        :: "r"(dst_smem), "l"(src), "r"(bytes), "r"(mbar) : "memory");
}

__global__ __launch_bounds__(WPB * 32) void transd_kernel(
    const char* __restrict__ ee,    // entity_emb      (row = 512B)
    const char* __restrict__ eep,   // entity_emb_p
    const char* __restrict__ re,    // relation_emb
    const char* __restrict__ rep,   // relation_emb_p
    const int* __restrict__ h,
    const int* __restrict__ r,
    const int* __restrict__ t,
    float4* __restrict__ out)       // [3 * NB * 32]
{
    // per-warp staging: 6 rows x 512B
    __shared__ __align__(16) float4 buf[WPB][6 * 32];
    __shared__ __align__(8) unsigned long long mbar[WPB];

    int wid  = threadIdx.x >> 5;
    unsigned lane = threadIdx.x & 31u;
    int gwarp = blockIdx.x * WPB + wid;
    if (gwarp >= NB) return;

    uint32_t mb = smem_u32(&mbar[wid]);

    if (lane == 0) {
        asm volatile("mbarrier.init.shared.b64 [%0], 1;" :: "r"(mb) : "memory");
        asm volatile("fence.proxy.async.shared::cta;" ::: "memory");
    }
    __syncwarp();

    if (lane == 0) {
        int hi = __ldg(&h[gwarp]);
        int ri = __ldg(&r[gwarp]);
        int ti = __ldg(&t[gwarp]);

        asm volatile("mbarrier.arrive.expect_tx.shared.b64 _, [%0], %1;"
                     :: "r"(mb), "r"(6u * ROW_BYTES) : "memory");

        uint32_t d0 = smem_u32(&buf[wid][0]);
        bulk_cp(d0 + 0u * ROW_BYTES, ee  + (size_t)hi * ROW_BYTES, ROW_BYTES, mb);
        bulk_cp(d0 + 1u * ROW_BYTES, eep + (size_t)hi * ROW_BYTES, ROW_BYTES, mb);
        bulk_cp(d0 + 2u * ROW_BYTES, ee  + (size_t)ti * ROW_BYTES, ROW_BYTES, mb);
        bulk_cp(d0 + 3u * ROW_BYTES, eep + (size_t)ti * ROW_BYTES, ROW_BYTES, mb);
        bulk_cp(d0 + 4u * ROW_BYTES, re  + (size_t)ri * ROW_BYTES, ROW_BYTES, mb);
        bulk_cp(d0 + 5u * ROW_BYTES, rep + (size_t)ri * ROW_BYTES, ROW_BYTES, mb);
    }

    // all lanes wait for completion (phase 0, single-shot)
    {
        uint32_t done;
        asm volatile(
            "{\n\t.reg .pred p;\n\t"
            "mbarrier.try_wait.parity.acquire.cta.shared::cta.b64 p, [%1], 0;\n\t"
            "selp.b32 %0, 1, 0, p;\n\t}"
            : "=r"(done) : "r"(mb) : "memory");
        if (!done) {
            asm volatile(
                "{\n\t.reg .pred P1;\n\t"
                "WL_%=:\n\t"
                "mbarrier.try_wait.parity.acquire.cta.shared::cta.b64 P1, [%0], 0, 0x989680;\n\t"
                "@P1 bra.uni WD_%=;\n\t"
                "bra.uni WL_%=;\n\t"
                "WD_%=:\n\t}"
                :: "r"(mb) : "memory");
        }
    }

    float4 hv = buf[wid][0 * 32 + lane];
    float4 hp = buf[wid][1 * 32 + lane];
    float4 tv = buf[wid][2 * 32 + lane];
    float4 tp = buf[wid][3 * 32 + lane];
    float4 rv = buf[wid][4 * 32 + lane];
    float4 rp = buf[wid][5 * 32 + lane];

    // 8 per-lane partials:
    // 0:|hv|^2 1:|hp|^2 2:|tv|^2 3:|tp|^2 4:|rv|^2 5:|rp|^2 6:<hp,hv> 7:<tp,tv>
    float p0 = dot4(hv, hv);
    float p1 = dot4(hp, hp);
    float p2 = dot4(tv, tv);
    float p3 = dot4(tp, tp);
    float p4 = dot4(rv, rv);
    float p5 = dot4(rp, rp);
    float p6 = dot4(hp, hv);
    float p7 = dot4(tp, tv);

    bool b0 = lane & 1u;
    bool b1 = lane & 2u;
    bool b2 = lane & 4u;

    // value-packing butterfly: 8 sums in 9 SHFLs
    float q0 = (b0 ? p1 : p0) + __shfl_xor_sync(FULL, b0 ? p0 : p1, 1);
    float q1 = (b0 ? p3 : p2) + __shfl_xor_sync(FULL, b0 ? p2 : p3, 1);
    float q2 = (b0 ? p5 : p4) + __shfl_xor_sync(FULL, b0 ? p4 : p5, 1);
    float q3 = (b0 ? p7 : p6) + __shfl_xor_sync(FULL, b0 ? p6 : p7, 1);

    float u0 = (b1 ? q1 : q0) + __shfl_xor_sync(FULL, b1 ? q0 : q1, 2);
    float u1 = (b1 ? q3 : q2) + __shfl_xor_sync(FULL, b1 ? q2 : q3, 2);

    float w = (b2 ? u1 : u0) + __shfl_xor_sync(FULL, b2 ? u0 : u1, 4);
    w += __shfl_xor_sync(FULL, w, 8);
    w += __shfl_xor_sync(FULL, w, 16);
    // every lane holds total_{lane&7}

    float rs = rscale(w);

    float c_hv = __shfl_sync(FULL, rs, 0);
    float c_hp = __shfl_sync(FULL, rs, 1);
    float c_tv = __shfl_sync(FULL, rs, 2);
    float c_tp = __shfl_sync(FULL, rs, 3);
    float c_rv = __shfl_sync(FULL, rs, 4);
    float c_rp = __shfl_sync(FULL, rs, 5);
    float d_h  = __shfl_sync(FULL, w, 6);
    float d_t  = __shfl_sync(FULL, w, 7);

    float a_h = c_rp * (d_h * c_hp * c_hv);
    float a_t = c_rp * (d_t * c_tp * c_tv);

    unsigned base = (unsigned)gwarp * DV + lane;

    float4 o;
    o.x = rp.x * a_h + hv.x * c_hv;
    o.y = rp.y * a_h + hv.y * c_hv;
    o.z = rp.z * a_h + hv.z * c_hv;
    o.w = rp.w * a_h + hv.w * c_hv;
    st_cs(&out[base], o);

    o.x = rv.x * c_rv; o.y = rv.y * c_rv; o.z = rv.z * c_rv; o.w = rv.w * c_rv;
    st_cs(&out[NB * DV + base], o);

    o.x = rp.x * a_t + tv.x * c_tv;
    o.y = rp.y * a_t + tv.y * c_tv;
    o.z = rp.z * a_t + tv.z * c_tv;
    o.w = rp.w * a_t + tv.w * c_tv;
    st_cs(&out[2u * NB * DV + base], o);
}

extern "C" void kernel_launch(void* const* d_in, const int* in_sizes, int n_in,
                              void* d_out, int out_size) {
    const char* ee  = (const char*)d_in[0];
    const char* eep = (const char*)d_in[1];
    const char* re  = (const char*)d_in[2];
    const char* rep = (const char*)d_in[3];
    const int* h = (const int*)d_in[4];
    const int* r = (const int*)d_in[5];
    const int* t = (const int*)d_in[6];

    int blocks = (NB + WPB - 1) / WPB;  // 2048 blocks of 128 threads
    transd_kernel<<<blocks, WPB * 32>>>(ee, eep, re, rep, h, r, t, (float4*)d_out);
}